// round 2
// baseline (speedup 1.0000x reference)
#include <cuda_runtime.h>
#include <cstdint>
#include <cstddef>

#define HH 4
#define CC 16
#define DIN 128
#define DOUT 64
#define N_AUTHOR 150000
#define N_PAPER  200000
#define N_OUTN   50000
#define NEG 0.2f

// ---------------- scratch layout (single __device__ arena, no allocs) -------
static constexpr size_t OFF_LA  = 0;                               // l_author 150000*64
static constexpr size_t OFF_LP  = OFF_LA  + (size_t)N_AUTHOR*DOUT; // l_paper  200000*64
static constexpr size_t OFF_SJW = OFF_LP  + (size_t)N_PAPER*DOUT;  // s_j writes (author) 150000*4
static constexpr size_t OFF_SJC = OFF_SJW + (size_t)N_AUTHOR*HH;   // s_j cites (paper)  200000*4
static constexpr size_t OFF_SIW = OFF_SJC + (size_t)N_PAPER*HH;    // s_i writes 50000*4
static constexpr size_t OFF_SIC = OFF_SIW + (size_t)N_OUTN*HH;     // s_i cites  50000*4
static constexpr size_t OFF_AGW = OFF_SIC + (size_t)N_OUTN*HH;     // agg writes 50000*64
static constexpr size_t OFF_AGC = OFF_AGW + (size_t)N_OUTN*DOUT;   // agg cites  50000*64
static constexpr size_t OFF_DNW = OFF_AGC + (size_t)N_OUTN*DOUT;   // denom writes 50000*4
static constexpr size_t OFF_DNC = OFF_DNW + (size_t)N_OUTN*HH;     // denom cites  50000*4
static constexpr size_t SCRATCH_FLOATS = OFF_DNC + (size_t)N_OUTN*HH;

__device__ float g_scratch[SCRATCH_FLOATS];

// ---------------- zero the accumulation region (agg + denom, contiguous) ----
__global__ void zero_kernel() {
    size_t start4 = OFF_AGW / 4;                 // OFF_AGW is 4-float aligned
    size_t n4 = (SCRATCH_FLOATS - OFF_AGW) / 4;  // all section sizes are multiples of 4
    float4* p = reinterpret_cast<float4*>(g_scratch) + start4;
    size_t i = (size_t)blockIdx.x * blockDim.x + threadIdx.x;
    size_t stride = (size_t)gridDim.x * blockDim.x;
    float4 z = make_float4(0.f, 0.f, 0.f, 0.f);
    for (; i < n4; i += stride) p[i] = z;
}

// ---------------- GEMM (M x 128) @ (128 x 64) + bias, fused per-node scores -
// Each thread computes one full output row (64 accumulators). W staged in smem
// (warp-broadcast LDS.128, FFMA-pipe bound). Epilogues compute the per-node
// halves of the edge attention logits:
//   s[row*H+h] = sum_c lrelu(acc[h*16+c]) * attn[h*2C + c]   (attn pre-offset)
__global__ __launch_bounds__(256) void gemm_kernel(
    const float* __restrict__ X, const float* __restrict__ W,
    const float* __restrict__ bias,
    size_t off_L, int store_L,
    size_t off_s0, const float* __restrict__ attn0,
    size_t off_s1, const float* __restrict__ attn1,
    int M)
{
    __shared__ float4 Ws[DIN * DOUT / 4];  // 32 KB, index [k*16 + n4]
    for (int i = threadIdx.x; i < DIN * DOUT / 4; i += 256)
        Ws[i] = reinterpret_cast<const float4*>(W)[i];
    __syncthreads();

    int row = blockIdx.x * 256 + threadIdx.x;
    if (row >= M) return;

    float acc[DOUT];
#pragma unroll
    for (int n = 0; n < DOUT; n++) acc[n] = __ldg(bias + n);

    const float4* Xr = reinterpret_cast<const float4*>(X + (size_t)row * DIN);
#pragma unroll 4
    for (int kk = 0; kk < DIN / 4; kk++) {
        float4 xv = __ldg(Xr + kk);
        float xs[4] = {xv.x, xv.y, xv.z, xv.w};
#pragma unroll
        for (int j = 0; j < 4; j++) {
            int k = kk * 4 + j;
#pragma unroll
            for (int n4 = 0; n4 < 16; n4++) {
                float4 w = Ws[k * 16 + n4];
                acc[n4 * 4 + 0] += xs[j] * w.x;
                acc[n4 * 4 + 1] += xs[j] * w.y;
                acc[n4 * 4 + 2] += xs[j] * w.z;
                acc[n4 * 4 + 3] += xs[j] * w.w;
            }
        }
    }

    if (store_L) {
        float4* Lr = reinterpret_cast<float4*>(g_scratch + off_L + (size_t)row * DOUT);
#pragma unroll
        for (int n4 = 0; n4 < 16; n4++)
            Lr[n4] = make_float4(acc[n4*4+0], acc[n4*4+1], acc[n4*4+2], acc[n4*4+3]);
    }

    if (attn0) {
        float* s0 = g_scratch + off_s0;
#pragma unroll
        for (int h = 0; h < HH; h++) {
            float s = 0.f;
#pragma unroll
            for (int c = 0; c < CC; c++) {
                float v = acc[h * CC + c];
                float lv = v > 0.f ? v : NEG * v;
                s += lv * __ldg(attn0 + h * 2 * CC + c);
            }
            s0[(size_t)row * HH + h] = s;
        }
    }
    if (attn1) {
        float* s1 = g_scratch + off_s1;
#pragma unroll
        for (int h = 0; h < HH; h++) {
            float s = 0.f;
#pragma unroll
            for (int c = 0; c < CC; c++) {
                float v = acc[h * CC + c];
                float lv = v > 0.f ? v : NEG * v;
                s += lv * __ldg(attn1 + h * 2 * CC + c);
            }
            s1[(size_t)row * HH + h] = s;
        }
    }
}

// ---------------- edge pass: single fused softmax-numerator aggregation -----
// Softmax is shift-invariant, so no segment_max pass: ea = exp(alpha),
// agg[dst] += x_j * ea, denom[dst,h] += ea. Warp per edge; atomicAdd with
// unused result lowers to RED.E.ADD.F32 (no return trip).
__global__ void edge_kernel(
    const int* __restrict__ src, const int* __restrict__ dst,
    size_t off_sj, size_t off_si, size_t off_L,
    size_t off_agg, size_t off_den, int E)
{
    const float* sj = g_scratch + off_sj;
    const float* si = g_scratch + off_si;
    const float* L  = g_scratch + off_L;
    float* agg = g_scratch + off_agg;
    float* den = g_scratch + off_den;

    int gtid = blockIdx.x * blockDim.x + threadIdx.x;
    int wid = gtid >> 5, lane = gtid & 31;
    int nw = (gridDim.x * blockDim.x) >> 5;
    int h = lane >> 3;  // lane covers channels 2*lane, 2*lane+1 -> head = lane/8

    for (int e = wid; e < E; e += nw) {
        int s = __ldg(src + e);
        int d = __ldg(dst + e);
        float a = __ldg(si + (size_t)d * HH + h) + __ldg(sj + (size_t)s * HH + h);
        float ea = __expf(a);
        float2 xj = *reinterpret_cast<const float2*>(L + (size_t)s * DOUT + 2 * lane);
        float* p = agg + (size_t)d * DOUT + 2 * lane;
        atomicAdd(p,     xj.x * ea);
        atomicAdd(p + 1, xj.y * ea);
        if ((lane & 7) == 0)
            atomicAdd(den + (size_t)d * HH + h, ea);
    }
}

// ---------------- final semantic attention (warp per output node) -----------
__global__ void final_kernel(
    const float* __restrict__ ral, const float* __restrict__ rar,
    float* __restrict__ out)
{
    const float* aggw = g_scratch + OFF_AGW;
    const float* aggc = g_scratch + OFF_AGC;
    const float* denw = g_scratch + OFF_DNW;
    const float* denc = g_scratch + OFF_DNC;
    const float* lp   = g_scratch + OFF_LP;

    int gtid = blockIdx.x * blockDim.x + threadIdx.x;
    int wid = gtid >> 5, lane = gtid & 31;
    int nw = (gridDim.x * blockDim.x) >> 5;
    int h = lane >> 3;
    int c0 = (2 * lane) & 15;

    for (int n = wid; n < N_OUTN; n += nw) {
        float invw = 1.f / (__ldg(denw + (size_t)n * HH + h) + 1e-16f);
        float invc = 1.f / (__ldg(denc + (size_t)n * HH + h) + 1e-16f);
        float2 ew = *reinterpret_cast<const float2*>(aggw + (size_t)n * DOUT + 2 * lane);
        float2 ec = *reinterpret_cast<const float2*>(aggc + (size_t)n * DOUT + 2 * lane);
        float2 se = *reinterpret_cast<const float2*>(lp   + (size_t)n * DOUT + 2 * lane);
        ew.x *= invw; ew.y *= invw;
        ec.x *= invc; ec.y *= invc;

        // partial dots for alpha_l (self·ral) and alpha_r[3]
        float rl0 = __ldg(ral + h * 16 + c0),       rl1 = __ldg(ral + h * 16 + c0 + 1);
        float r00 = __ldg(rar +   0 + h * 16 + c0), r01 = __ldg(rar +   0 + h * 16 + c0 + 1);
        float r10 = __ldg(rar +  64 + h * 16 + c0), r11 = __ldg(rar +  64 + h * 16 + c0 + 1);
        float r20 = __ldg(rar + 128 + h * 16 + c0), r21 = __ldg(rar + 128 + h * 16 + c0 + 1);
        float pl = se.x * rl0 + se.y * rl1;
        float p0 = ew.x * r00 + ew.y * r01;
        float p1 = ec.x * r10 + ec.y * r11;
        float p2 = se.x * r20 + se.y * r21;

        // reduce within 8-lane head group
#pragma unroll
        for (int m = 1; m < 8; m <<= 1) {
            pl += __shfl_xor_sync(0xffffffffu, pl, m);
            p0 += __shfl_xor_sync(0xffffffffu, p0, m);
            p1 += __shfl_xor_sync(0xffffffffu, p1, m);
            p2 += __shfl_xor_sync(0xffffffffu, p2, m);
        }

        float a0 = pl + p0; a0 = a0 > 0.f ? a0 : NEG * a0;
        float a1 = pl + p1; a1 = a1 > 0.f ? a1 : NEG * a1;
        float a2 = pl + p2; a2 = a2 > 0.f ? a2 : NEG * a2;
        float mx = fmaxf(a0, fmaxf(a1, a2));
        float e0 = __expf(a0 - mx), e1 = __expf(a1 - mx), e2 = __expf(a2 - mx);
        float inv = 1.f / (e0 + e1 + e2);
        float b0 = e0 * inv, b1 = e1 * inv, b2 = e2 * inv;

        float2 o;
        o.x = fmaxf(ew.x * b0 + ec.x * b1 + se.x * b2, 0.f);
        o.y = fmaxf(ew.y * b0 + ec.y * b1 + se.y * b2, 0.f);
        *reinterpret_cast<float2*>(out + (size_t)n * DOUT + 2 * lane) = o;
    }
}

// ---------------- launch --------------------------------------------------
extern "C" void kernel_launch(void* const* d_in, const int* in_sizes, int n_in,
                              void* d_out, int out_size)
{
    const float* x_author = (const float*)d_in[0];
    const float* x_paper  = (const float*)d_in[1];
    const float* Wla = (const float*)d_in[2];
    const float* bla = (const float*)d_in[3];
    const float* Wlp = (const float*)d_in[4];
    const float* blp = (const float*)d_in[5];
    const float* Wrp = (const float*)d_in[6];
    const float* brp = (const float*)d_in[7];
    const float* attn_w = (const float*)d_in[8];
    const float* attn_c = (const float*)d_in[9];
    const float* ral = (const float*)d_in[10];
    const float* rar = (const float*)d_in[11];
    const int* srcw = (const int*)d_in[12];
    const int* dstw = (const int*)d_in[13];
    const int* srcc = (const int*)d_in[14];
    const int* dstc = (const int*)d_in[15];
    int E = in_sizes[12];
    float* out = (float*)d_out;

    zero_kernel<<<2048, 256>>>();

    // l_author = x_author @ Wla + bla ; fused s_j(writes) via attn_w[:, C:]
    gemm_kernel<<<(N_AUTHOR + 255) / 256, 256>>>(
        x_author, Wla, bla, OFF_LA, 1, OFF_SJW, attn_w + CC, 0, nullptr, N_AUTHOR);
    // l_paper = x_paper @ Wlp + blp ; fused s_j(cites) via attn_c[:, C:]
    gemm_kernel<<<(N_PAPER + 255) / 256, 256>>>(
        x_paper, Wlp, blp, OFF_LP, 1, OFF_SJC, attn_c + CC, 0, nullptr, N_PAPER);
    // r_paper scores only (matrix itself is never consumed downstream):
    // s_i(writes) via attn_w[:, :C], s_i(cites) via attn_c[:, :C]
    gemm_kernel<<<(N_OUTN + 255) / 256, 256>>>(
        x_paper, Wrp, brp, 0, 0, OFF_SIW, attn_w, OFF_SIC, attn_c, N_OUTN);

    edge_kernel<<<2960, 256>>>(srcw, dstw, OFF_SJW, OFF_SIW, OFF_LA, OFF_AGW, OFF_DNW, E);
    edge_kernel<<<2960, 256>>>(srcc, dstc, OFF_SJC, OFF_SIC, OFF_LP, OFF_AGC, OFF_DNC, E);

    final_kernel<<<6250, 256>>>(ral, rar, out);
}

// round 4
// speedup vs baseline: 1.3554x; 1.3554x over previous
#include <cuda_runtime.h>
#include <cstdint>
#include <cstddef>

#define HH 4
#define CC 16
#define DIN 128
#define DOUT 64
#define N_AUTHOR 150000
#define N_PAPER  200000
#define N_OUTN   50000
#define NEG 0.2f

// ---------------- scratch layout (single __device__ arena, no allocs) -------
static constexpr size_t OFF_LA  = 0;                               // l_author 150000*64
static constexpr size_t OFF_LP  = OFF_LA  + (size_t)N_AUTHOR*DOUT; // l_paper  200000*64
static constexpr size_t OFF_RP  = OFF_LP  + (size_t)N_PAPER*DOUT;  // r_paper  50000*64
static constexpr size_t OFF_SJW = OFF_RP  + (size_t)N_OUTN*DOUT;   // s_j writes 150000*4
static constexpr size_t OFF_SJC = OFF_SJW + (size_t)N_AUTHOR*HH;   // s_j cites  200000*4
static constexpr size_t OFF_SIW = OFF_SJC + (size_t)N_PAPER*HH;    // s_i writes 50000*4
static constexpr size_t OFF_SIC = OFF_SIW + (size_t)N_OUTN*HH;     // s_i cites  50000*4
static constexpr size_t OFF_AGW = OFF_SIC + (size_t)N_OUTN*HH;     // agg writes 50000*64
static constexpr size_t OFF_AGC = OFF_AGW + (size_t)N_OUTN*DOUT;   // agg cites  50000*64
static constexpr size_t OFF_DNW = OFF_AGC + (size_t)N_OUTN*DOUT;   // denom writes 50000*4
static constexpr size_t OFF_DNC = OFF_DNW + (size_t)N_OUTN*HH;     // denom cites  50000*4
static constexpr size_t SCRATCH_FLOATS = OFF_DNC + (size_t)N_OUTN*HH;

__device__ float g_scratch[SCRATCH_FLOATS];

// ---------------- helpers ---------------------------------------------------
__device__ __forceinline__ unsigned tf32_of(float x) {
    unsigned r;
    asm("cvt.rna.tf32.f32 %0, %1;" : "=r"(r) : "f"(x));
    return r;
}

__device__ __forceinline__ void mma_tf32(float d[4], const unsigned a[4], const unsigned b[2]) {
    asm volatile(
        "mma.sync.aligned.m16n8k8.row.col.f32.tf32.tf32.f32 "
        "{%0,%1,%2,%3}, {%4,%5,%6,%7}, {%8,%9}, {%0,%1,%2,%3};"
        : "+f"(d[0]), "+f"(d[1]), "+f"(d[2]), "+f"(d[3])
        : "r"(a[0]), "r"(a[1]), "r"(a[2]), "r"(a[3]), "r"(b[0]), "r"(b[1]));
}

// ---------------- zero the accumulation region (agg + denom, contiguous) ----
__global__ void zero_kernel() {
    size_t start4 = OFF_AGW / 4;
    size_t n4 = (SCRATCH_FLOATS - OFF_AGW) / 4;
    float4* p = reinterpret_cast<float4*>(g_scratch) + start4;
    size_t i = (size_t)blockIdx.x * blockDim.x + threadIdx.x;
    size_t stride = (size_t)gridDim.x * blockDim.x;
    float4 z = make_float4(0.f, 0.f, 0.f, 0.f);
    for (; i < n4; i += stride) p[i] = z;
}

// ---------------- tensor-core GEMM: (M x 128) @ (128 x 64) + bias -----------
// 3xTF32 hi/lo split (Ah*Bh + Ah*Bl + Al*Bh) for ~fp32 accuracy.
// Block tile 128x64, 8 warps in 4x2. K chunked by 32 via padded smem:
//   Xs stride 36 floats -> A-frag banks (4*row+k)%32 all distinct
//   Ws stride 68 floats -> B-frag banks (4*k+col)%32 all distinct
__global__ __launch_bounds__(256, 2) void gemm_tc_kernel(
    const float* __restrict__ X, const float* __restrict__ W,
    const float* __restrict__ bias, size_t off_L, int M)
{
    __shared__ float Xs[128 * 36];
    __shared__ float Ws[32 * 68];

    int tid = threadIdx.x;
    int wid = tid >> 5, lane = tid & 31;
    int warpm = wid >> 1, warpn = wid & 1;
    int g = lane >> 2, t = lane & 3;
    int blockRow = blockIdx.x * 128;

    float acc[2][4][4];
#pragma unroll
    for (int mt = 0; mt < 2; mt++)
#pragma unroll
        for (int nt = 0; nt < 4; nt++)
#pragma unroll
            for (int i = 0; i < 4; i++) acc[mt][nt][i] = 0.f;

    const float4* Xg = reinterpret_cast<const float4*>(X);
    const float4* Wg = reinterpret_cast<const float4*>(W);
    float4* Xs4 = reinterpret_cast<float4*>(Xs);
    float4* Ws4 = reinterpret_cast<float4*>(Ws);

    int xrow = tid >> 1;       // 0..127
    int xpart = tid & 1;       // 0..1 (4 float4 each)
    bool xvalid = (blockRow + xrow) < M;

#pragma unroll 1
    for (int c = 0; c < 4; c++) {           // K chunks of 32
        __syncthreads();
#pragma unroll
        for (int j = 0; j < 4; j++) {
            float4 v = make_float4(0.f, 0.f, 0.f, 0.f);
            if (xvalid)
                v = __ldg(&Xg[(size_t)(blockRow + xrow) * 32 + c * 8 + xpart * 4 + j]);
            Xs4[xrow * 9 + xpart * 4 + j] = v;
        }
#pragma unroll
        for (int i = tid; i < 512; i += 256) {
            int k = i >> 4, n4 = i & 15;
            Ws4[k * 17 + n4] = __ldg(&Wg[(size_t)(c * 32 + k) * 16 + n4]);
        }
        __syncthreads();

#pragma unroll
        for (int ks = 0; ks < 4; ks++) {
            int k = ks * 8;
            unsigned Ah[2][4], Al[2][4], Bh[4][2], Bl[4][2];
#pragma unroll
            for (int mt = 0; mt < 2; mt++) {
                int r0 = warpm * 32 + mt * 16 + g;
#pragma unroll
                for (int i = 0; i < 4; i++) {
                    int rr = r0 + (i & 1) * 8;
                    int kk = k + t + (i >> 1) * 4;
                    float v = Xs[rr * 36 + kk];
                    unsigned hi = tf32_of(v);
                    Ah[mt][i] = hi;
                    Al[mt][i] = tf32_of(v - __uint_as_float(hi));
                }
            }
#pragma unroll
            for (int nt = 0; nt < 4; nt++) {
                int c0 = warpn * 32 + nt * 8 + g;
#pragma unroll
                for (int i = 0; i < 2; i++) {
                    int kk = k + t + i * 4;
                    float v = Ws[kk * 68 + c0];
                    unsigned hi = tf32_of(v);
                    Bh[nt][i] = hi;
                    Bl[nt][i] = tf32_of(v - __uint_as_float(hi));
                }
            }
#pragma unroll
            for (int mt = 0; mt < 2; mt++)
#pragma unroll
                for (int nt = 0; nt < 4; nt++) {
                    mma_tf32(acc[mt][nt], Ah[mt], Bh[nt]);
                    mma_tf32(acc[mt][nt], Ah[mt], Bl[nt]);
                    mma_tf32(acc[mt][nt], Al[mt], Bh[nt]);
                }
        }
    }

    // epilogue: bias + store (float2 per fragment pair)
    float* L = g_scratch + off_L;
#pragma unroll
    for (int mt = 0; mt < 2; mt++) {
        int row0 = blockRow + warpm * 32 + mt * 16 + g;
#pragma unroll
        for (int nt = 0; nt < 4; nt++) {
            int col0 = warpn * 32 + nt * 8 + 2 * t;
            float b0 = __ldg(bias + col0), b1 = __ldg(bias + col0 + 1);
            if (row0 < M) {
                float2 v = make_float2(acc[mt][nt][0] + b0, acc[mt][nt][1] + b1);
                *reinterpret_cast<float2*>(L + (size_t)row0 * DOUT + col0) = v;
            }
            if (row0 + 8 < M) {
                float2 v = make_float2(acc[mt][nt][2] + b0, acc[mt][nt][3] + b1);
                *reinterpret_cast<float2*>(L + (size_t)(row0 + 8) * DOUT + col0) = v;
            }
        }
    }
}

// ---------------- per-node attention scores from L --------------------------
// s[row,h] = sum_c lrelu(L[row, h*16+c]) * attn[h*2C + c]  (attn pre-offset)
__global__ void score_kernel(
    size_t off_L, int M,
    size_t off_s0, const float* __restrict__ attn0,
    size_t off_s1, const float* __restrict__ attn1)
{
    int idx = blockIdx.x * blockDim.x + threadIdx.x;
    int row = idx >> 2, h = idx & 3;
    if (row >= M) return;
    const float4* Lr = reinterpret_cast<const float4*>(g_scratch + off_L + (size_t)row * DOUT + h * CC);
    float v[CC];
#pragma unroll
    for (int j = 0; j < 4; j++) {
        float4 x = Lr[j];
        v[j*4+0] = x.x; v[j*4+1] = x.y; v[j*4+2] = x.z; v[j*4+3] = x.w;
    }
    float lv[CC];
#pragma unroll
    for (int c = 0; c < CC; c++) lv[c] = v[c] > 0.f ? v[c] : NEG * v[c];

    float s0 = 0.f;
#pragma unroll
    for (int c = 0; c < CC; c++) s0 += lv[c] * __ldg(attn0 + h * 2 * CC + c);
    g_scratch[off_s0 + (size_t)row * HH + h] = s0;

    if (attn1) {
        float s1 = 0.f;
#pragma unroll
        for (int c = 0; c < CC; c++) s1 += lv[c] * __ldg(attn1 + h * 2 * CC + c);
        g_scratch[off_s1 + (size_t)row * HH + h] = s1;
    }
}

// ---------------- edge pass: single fused softmax-numerator aggregation -----
// Softmax is shift-invariant: ea = exp(alpha), agg[dst] += x_j*ea (RED),
// denom[dst,h] += ea. Warp per edge.
__global__ void edge_kernel(
    const int* __restrict__ src, const int* __restrict__ dst,
    size_t off_sj, size_t off_si, size_t off_L,
    size_t off_agg, size_t off_den, int E)
{
    const float* sj = g_scratch + off_sj;
    const float* si = g_scratch + off_si;
    const float* L  = g_scratch + off_L;
    float* agg = g_scratch + off_agg;
    float* den = g_scratch + off_den;

    int gtid = blockIdx.x * blockDim.x + threadIdx.x;
    int wid = gtid >> 5, lane = gtid & 31;
    int nw = (gridDim.x * blockDim.x) >> 5;
    int h = lane >> 3;

    for (int e = wid; e < E; e += nw) {
        int s = __ldg(src + e);
        int d = __ldg(dst + e);
        float a = __ldg(si + (size_t)d * HH + h) + __ldg(sj + (size_t)s * HH + h);
        float ea = __expf(a);
        float2 xj = *reinterpret_cast<const float2*>(L + (size_t)s * DOUT + 2 * lane);
        float* p = agg + (size_t)d * DOUT + 2 * lane;
        atomicAdd(p,     xj.x * ea);
        atomicAdd(p + 1, xj.y * ea);
        if ((lane & 7) == 0)
            atomicAdd(den + (size_t)d * HH + h, ea);
    }
}

// ---------------- final semantic attention (warp per output node) -----------
__global__ void final_kernel(
    const float* __restrict__ ral, const float* __restrict__ rar,
    float* __restrict__ out)
{
    const float* aggw = g_scratch + OFF_AGW;
    const float* aggc = g_scratch + OFF_AGC;
    const float* denw = g_scratch + OFF_DNW;
    const float* denc = g_scratch + OFF_DNC;
    const float* lp   = g_scratch + OFF_LP;

    int gtid = blockIdx.x * blockDim.x + threadIdx.x;
    int wid = gtid >> 5, lane = gtid & 31;
    int nw = (gridDim.x * blockDim.x) >> 5;
    int h = lane >> 3;
    int c0 = (2 * lane) & 15;

    for (int n = wid; n < N_OUTN; n += nw) {
        float invw = 1.f / (__ldg(denw + (size_t)n * HH + h) + 1e-16f);
        float invc = 1.f / (__ldg(denc + (size_t)n * HH + h) + 1e-16f);
        float2 ew = *reinterpret_cast<const float2*>(aggw + (size_t)n * DOUT + 2 * lane);
        float2 ec = *reinterpret_cast<const float2*>(aggc + (size_t)n * DOUT + 2 * lane);
        float2 se = *reinterpret_cast<const float2*>(lp   + (size_t)n * DOUT + 2 * lane);
        ew.x *= invw; ew.y *= invw;
        ec.x *= invc; ec.y *= invc;

        float rl0 = __ldg(ral + h * 16 + c0),       rl1 = __ldg(ral + h * 16 + c0 + 1);
        float r00 = __ldg(rar +   0 + h * 16 + c0), r01 = __ldg(rar +   0 + h * 16 + c0 + 1);
        float r10 = __ldg(rar +  64 + h * 16 + c0), r11 = __ldg(rar +  64 + h * 16 + c0 + 1);
        float r20 = __ldg(rar + 128 + h * 16 + c0), r21 = __ldg(rar + 128 + h * 16 + c0 + 1);
        float pl = se.x * rl0 + se.y * rl1;
        float p0 = ew.x * r00 + ew.y * r01;
        float p1 = ec.x * r10 + ec.y * r11;
        float p2 = se.x * r20 + se.y * r21;

#pragma unroll
        for (int m = 1; m < 8; m <<= 1) {
            pl += __shfl_xor_sync(0xffffffffu, pl, m);
            p0 += __shfl_xor_sync(0xffffffffu, p0, m);
            p1 += __shfl_xor_sync(0xffffffffu, p1, m);
            p2 += __shfl_xor_sync(0xffffffffu, p2, m);
        }

        float a0 = pl + p0; a0 = a0 > 0.f ? a0 : NEG * a0;
        float a1 = pl + p1; a1 = a1 > 0.f ? a1 : NEG * a1;
        float a2 = pl + p2; a2 = a2 > 0.f ? a2 : NEG * a2;
        float mx = fmaxf(a0, fmaxf(a1, a2));
        float e0 = __expf(a0 - mx), e1 = __expf(a1 - mx), e2 = __expf(a2 - mx);
        float inv = 1.f / (e0 + e1 + e2);
        float b0 = e0 * inv, b1 = e1 * inv, b2 = e2 * inv;

        float2 o;
        o.x = fmaxf(ew.x * b0 + ec.x * b1 + se.x * b2, 0.f);
        o.y = fmaxf(ew.y * b0 + ec.y * b1 + se.y * b2, 0.f);
        *reinterpret_cast<float2*>(out + (size_t)n * DOUT + 2 * lane) = o;
    }
}

// ---------------- launch --------------------------------------------------
extern "C" void kernel_launch(void* const* d_in, const int* in_sizes, int n_in,
                              void* d_out, int out_size)
{
    const float* x_author = (const float*)d_in[0];
    const float* x_paper  = (const float*)d_in[1];
    const float* Wla = (const float*)d_in[2];
    const float* bla = (const float*)d_in[3];
    const float* Wlp = (const float*)d_in[4];
    const float* blp = (const float*)d_in[5];
    const float* Wrp = (const float*)d_in[6];
    const float* brp = (const float*)d_in[7];
    const float* attn_w = (const float*)d_in[8];
    const float* attn_c = (const float*)d_in[9];
    const float* ral = (const float*)d_in[10];
    const float* rar = (const float*)d_in[11];
    const int* srcw = (const int*)d_in[12];
    const int* dstw = (const int*)d_in[13];
    const int* srcc = (const int*)d_in[14];
    const int* dstc = (const int*)d_in[15];
    int E = in_sizes[12];
    float* out = (float*)d_out;

    zero_kernel<<<2048, 256>>>();

    gemm_tc_kernel<<<(N_AUTHOR + 127) / 128, 256>>>(x_author, Wla, bla, OFF_LA, N_AUTHOR);
    gemm_tc_kernel<<<(N_PAPER  + 127) / 128, 256>>>(x_paper,  Wlp, blp, OFF_LP, N_PAPER);
    gemm_tc_kernel<<<(N_OUTN   + 127) / 128, 256>>>(x_paper,  Wrp, brp, OFF_RP, N_OUTN);

    score_kernel<<<(N_AUTHOR * HH + 255) / 256, 256>>>(OFF_LA, N_AUTHOR, OFF_SJW, attn_w + CC, 0, nullptr);
    score_kernel<<<(N_PAPER  * HH + 255) / 256, 256>>>(OFF_LP, N_PAPER,  OFF_SJC, attn_c + CC, 0, nullptr);
    score_kernel<<<(N_OUTN   * HH + 255) / 256, 256>>>(OFF_RP, N_OUTN,   OFF_SIW, attn_w, OFF_SIC, attn_c);

    edge_kernel<<<2960, 256>>>(srcw, dstw, OFF_SJW, OFF_SIW, OFF_LA, OFF_AGW, OFF_DNW, E);
    edge_kernel<<<2960, 256>>>(srcc, dstc, OFF_SJC, OFF_SIC, OFF_LP, OFF_AGC, OFF_DNC, E);

    final_kernel<<<6250, 256>>>(ral, rar, out);
}